// round 11
// baseline (speedup 1.0000x reference)
#include <cuda_runtime.h>
#include <cstdint>

// ---------------------------------------------------------------------------
// Heisenberg-collapsed circuit:
//   <Z0> = e2x*e3x + (e0*e1) * (e2y*e3x + e2z)
// Round 11: persistent grid-stride eval. 296 CTAs (2 per SM, single
// placement wave) x 256 threads; each thread processes ~7 samples in a
// grid-stride loop with software-pipelined loads. Tests the hypothesis that
// the config-invariant ~6.4us eval floor is CTA launch/drain ramp.
// K constants via PDL-overlapped precompute kernel (R9/R10 structure).
// ---------------------------------------------------------------------------

// K layout (20 floats, 16B aligned; loaded as 5 float4):
//  [0..2]  wire0: C, R, -delta      [3..5]   wire1: C, R, -delta
//  [6..8]  e2x: K0,K1,K2            [9..11]  e2y: K0,K1,K2
//  [12..14]e2z: K0,K1,K2            [15..17] wire3: C, R, -delta
__device__ __align__(16) float g_K[20];

struct Cpx { float r, i; };
__device__ __forceinline__ Cpx cmul(Cpx a, Cpx b) { return {a.r*b.r - a.i*b.i, a.r*b.i + a.i*b.r}; }
__device__ __forceinline__ Cpx cconj(Cpx a)       { return {a.r, -a.i}; }
__device__ __forceinline__ Cpx cadd(Cpx a, Cpx b) { return {a.r + b.r, a.i + b.i}; }
__device__ __forceinline__ Cpx csub(Cpx a, Cpx b) { return {a.r - b.r, a.i - b.i}; }
__device__ __forceinline__ Cpx cmuli(Cpx a)       { return {-a.i, a.r}; }   // i*a

__device__ void rot_mat(const float* __restrict__ w, Cpx R[4]) {
    float phi = w[0], th = w[1], om = w[2];
    float c = cosf(0.5f * th), s = sinf(0.5f * th);
    float a = 0.5f * (phi + om), b = 0.5f * (phi - om);
    Cpx ep = { cosf(a), -sinf(a) };
    Cpx em = { cosf(b),  sinf(b) };
    R[0] = {  ep.r * c,  ep.i * c };
    R[1] = { -em.r * s, -em.i * s };
    R[2] = {  em.r * s, -em.i * s };
    R[3] = {  ep.r * c, -ep.i * c };
}

__device__ void exp_coeffs(const Cpx R[4], int P, float scale, float* K) {
    float N00, N11;
    Cpx N01;
    if (P == 2) {            // Z
        N00 = (R[0].r*R[0].r + R[0].i*R[0].i) - (R[2].r*R[2].r + R[2].i*R[2].i);
        N01 = csub(cmul(cconj(R[0]), R[1]), cmul(cconj(R[2]), R[3]));
        N11 = (R[1].r*R[1].r + R[1].i*R[1].i) - (R[3].r*R[3].r + R[3].i*R[3].i);
    } else if (P == 0) {     // X
        Cpx z02 = cmul(cconj(R[0]), R[2]);
        Cpx z13 = cmul(cconj(R[1]), R[3]);
        N00 = 2.0f * z02.r;
        N01 = cadd(cmul(cconj(R[0]), R[3]), cmul(cconj(R[2]), R[1]));
        N11 = 2.0f * z13.r;
    } else {                 // Y
        Cpx z02 = cmul(cconj(R[0]), R[2]);
        Cpx z13 = cmul(cconj(R[1]), R[3]);
        N00 = 2.0f * z02.i;
        Cpx t1 = cmuli(cmul(cconj(R[0]), R[3]));
        Cpx t2 = cmuli(cmul(cconj(R[2]), R[1]));
        N01 = csub(t2, t1);
        N11 = 2.0f * z13.i;
    }
    K[0] = 0.5f * (N00 + N11) * scale;
    K[1] = 0.5f * (N00 - N11) * scale;
    K[2] = N01.i * scale;
}

__global__ void precompute_k(const float* __restrict__ w) {
    int t = threadIdx.x;
    if (t >= 6) return;

    int wire = (t == 0) ? 0 : (t == 1) ? 1 : (t == 5) ? 3 : 2;
    int P    = (t <= 1) ? 2 : (t == 2) ? 0 : (t == 3) ? 1 : (t == 4) ? 2 : 0;

    float scale = 1.0f;
    if (t >= 2 && t <= 4) {
        Cpx R1[4];
        rot_mat(w + (1 * 4 + 2) * 3, R1);
        float M00 = (R1[0].r*R1[0].r + R1[0].i*R1[0].i)
                  - (R1[2].r*R1[2].r + R1[2].i*R1[2].i);
        Cpx M01 = csub(cmul(cconj(R1[0]), R1[1]), cmul(cconj(R1[2]), R1[3]));
        scale = (t == 2) ? M01.r : (t == 3) ? -M01.i : M00;
    }

    Cpx R[4];
    rot_mat(w + wire * 3, R);
    float K[3];
    exp_coeffs(R, P, scale, K);

    int base = t * 3;
    if (t == 0 || t == 1 || t == 5) {
        float Rm = sqrtf(K[1] * K[1] + K[2] * K[2]);
        float nd = -atan2f(K[2], K[1]);
        g_K[base + 0] = K[0];
        g_K[base + 1] = Rm;
        g_K[base + 2] = nd;
    } else {
        g_K[base + 0] = K[0];
        g_K[base + 1] = K[1];
        g_K[base + 2] = K[2];
    }
    if (t == 0) { g_K[18] = 0.0f; g_K[19] = 0.0f; }
}

__device__ __forceinline__ float eval_sample(float4 xv,
                                             float4 ka, float4 kb, float4 kc,
                                             float4 kd, float4 ke) {
    float e0 = fmaf(ka.y, __cosf(xv.x + ka.z), ka.x);
    float e1 = fmaf(kb.x, __cosf(xv.y + kb.y), ka.w);
    float e3 = fmaf(ke.x, __cosf(xv.w + ke.y), kd.w);
    float s2, c2;
    __sincosf(xv.z, &s2, &c2);
    float e2x = fmaf(kb.w, c2, fmaf(kc.x, s2, kb.z));
    float e2y = fmaf(kc.z, c2, fmaf(kc.w, s2, kc.y));
    float e2z = fmaf(kd.y, c2, fmaf(kd.z, s2, kd.x));
    return fmaf(e0 * e1, fmaf(e2y, e3, e2z), e2x * e3);
}

static constexpr int N_CTAS   = 296;   // 2 per SM, single placement wave
static constexpr int N_THREADS = 256;

__global__ __launch_bounds__(N_THREADS)
void quantum_eval_persist(const float4* __restrict__ x,
                          float* __restrict__ out, int M) {
    const int stride = N_CTAS * N_THREADS;             // 75776
    int t0 = blockIdx.x * N_THREADS + threadIdx.x;

    // Issue the first two loads before waiting on the precompute kernel —
    // their DRAM latency overlaps the PDL-primary execution.
    float4 xa, xb;
    bool va = (t0 < M), vb = (t0 + stride < M);
    if (va) xa = __ldg(&x[t0]);
    if (vb) xb = __ldg(&x[t0 + stride]);

    cudaGridDependencySynchronize();
    const float4* kp = (const float4*)g_K;
    float4 ka = kp[0];
    float4 kb = kp[1];
    float4 kc = kp[2];
    float4 kd = kp[3];
    float4 ke = kp[4];

    // Software-pipelined grid-stride: keep 2 loads in flight; stores retire
    // behind. M = 524288 -> ceil(M/stride) = 7 iterations per thread.
    int i = t0;
    while (va) {
        // prefetch i + 2*stride into the slot we're about to free
        float4 xc;
        bool vc = (i + 2 * stride < M);
        if (vc) xc = __ldg(&x[i + 2 * stride]);

        out[i] = eval_sample(xa, ka, kb, kc, kd, ke);

        xa = xb; va = vb;
        xb = xc; vb = vc;
        i += stride;
    }
}

extern "C" void kernel_launch(void* const* d_in, const int* in_sizes, int n_in,
                              void* d_out, int out_size) {
    const float* x = (const float*)d_in[0];        // (64, 8192, 4) fp32
    const float* weights = (const float*)d_in[1];  // (2, 4, 3) fp32
    float* out = (float*)d_out;                    // (64, 8192, 1) fp32

    int M = in_sizes[0] / 4;                       // 524288 samples

    precompute_k<<<1, 32>>>(weights);

    cudaLaunchConfig_t cfg = {};
    cfg.gridDim  = dim3(N_CTAS, 1, 1);
    cfg.blockDim = dim3(N_THREADS, 1, 1);
    cfg.dynamicSmemBytes = 0;
    cfg.stream = 0;
    cudaLaunchAttribute attrs[1];
    attrs[0].id = cudaLaunchAttributeProgrammaticStreamSerialization;
    attrs[0].val.programmaticStreamSerializationAllowed = 1;
    cfg.attrs = attrs;
    cfg.numAttrs = 1;

    const float4* xv = (const float4*)x;
    cudaLaunchKernelEx(&cfg, quantum_eval_persist, xv, out, M);
}